// round 15
// baseline (speedup 1.0000x reference)
#include <cuda_runtime.h>
#include <cuda_fp16.h>
#include <math.h>
#include <stdint.h>

#define BB   64
#define TT   512
#define DD   512
#define UU   1024
#define G4   4096
#define NCTA 128

__device__ float  g_xg[(size_t)BB * TT * G4];   // [t][b][4096]
__device__ __align__(16) __half g_xh[(size_t)BB * TT * DD];
__device__ __align__(16) __half g_hh[2][BB * UU];
__device__ volatile unsigned g_gen; __device__ unsigned g_pad1[31];
__device__ unsigned g_cnt;          __device__ unsigned g_pad2[31];

// ---------------- helpers ---------------------------------------------------
__device__ __forceinline__ void mma16(float c[4], unsigned a0, unsigned a1,
                                      unsigned a2, unsigned a3,
                                      unsigned b0, unsigned b1) {
    asm volatile(
        "mma.sync.aligned.m16n8k16.row.col.f32.f16.f16.f32 "
        "{%0,%1,%2,%3}, {%4,%5,%6,%7}, {%8,%9}, {%0,%1,%2,%3};"
        : "+f"(c[0]), "+f"(c[1]), "+f"(c[2]), "+f"(c[3])
        : "r"(a0), "r"(a1), "r"(a2), "r"(a3), "r"(b0), "r"(b1));
}
__device__ __forceinline__ uint4 ldsm4(unsigned addr) {
    uint4 r;
    asm volatile("ldmatrix.sync.aligned.m8n8.x4.shared.b16 {%0,%1,%2,%3}, [%4];"
                 : "=r"(r.x), "=r"(r.y), "=r"(r.z), "=r"(r.w) : "r"(addr));
    return r;
}
__device__ __forceinline__ void cp16(unsigned dst, const void* src) {
    asm volatile("cp.async.cg.shared.global [%0], [%1], 16;" :: "r"(dst), "l"(src));
}
__device__ __forceinline__ void cp_commit() {
    asm volatile("cp.async.commit_group;");
}
__device__ __forceinline__ unsigned smem_u32(const void* p) {
    unsigned a;
    asm("{ .reg .u64 t; cvta.to.shared.u64 t, %1; cvt.u32.u64 %0, t; }" : "=r"(a) : "l"(p));
    return a;
}
__device__ __forceinline__ int slot_perm(int slot5) {
    int s = slot5 >> 4, p = slot5 & 15;
    int lcp = (p < 8) ? (p >> 1) : ((p - 8) >> 1);
    int add = (p < 8) ? 0 : 2;
    return 8 * lcp + 4 * s + add + (p & 1);
}
// fast activations (R9/R10-validated)
__device__ __forceinline__ float fsig(float x) {
    float e, r;
    asm("ex2.approx.f32 %0, %1;" : "=f"(e) : "f"(-1.4426950408889634f * x));
    asm("rcp.approx.f32 %0, %1;" : "=f"(r) : "f"(1.0f + e));
    return r;
}
__device__ __forceinline__ float ftanh_(float x) {
    float e, r;
    asm("ex2.approx.f32 %0, %1;" : "=f"(e) : "f"(2.8853900817779268f * x));
    asm("rcp.approx.f32 %0, %1;" : "=f"(r) : "f"(1.0f + e));
    return 1.0f - 2.0f * r;
}

// ============== THE single fused persistent kernel ==============
#define XG_WS 520                      // fp16 slots per n-row in xg phase
#define HS_STRIDE 1032
#define WT_STRIDE 1032
#define WT_BYTES  (32 * WT_STRIDE * 2)
#define HS_BYTES  (64 * HS_STRIDE * 2)
#define SMEM_BYTES (WT_BYTES + HS_BYTES + 64 * 33 * 4 + 512 * 4)

__global__ __launch_bounds__(256) void lstm_persist(
    const float* __restrict__ x,  const float* __restrict__ Wx,
    const float* __restrict__ bias,
    const float* __restrict__ Wh, const float* __restrict__ h0,
    const float* __restrict__ c0, float* __restrict__ out)
{
    extern __shared__ char smraw[];
    __half* Wt = (__half*)smraw;                         // persist: Wh slice / xg: Wx slice
    __half* Hs = (__half*)(smraw + WT_BYTES);
    float*  Gs = (float*)(smraw + WT_BYTES + HS_BYTES);
    float*  Cl = Gs + 64 * 33;

    const int tid  = threadIdx.x;
    const int warp = tid >> 5, lane = tid & 31;
    const int lr = lane >> 2, lc = lane & 3;
    const int mo = (warp & 3) * 16;
    const int no = (warp >> 2) * 16;
    const int u0 = blockIdx.x * 8;

    // helper: full grid barrier (tid0 arrive+poll)
    auto grid_bar = [&]() {
        __syncthreads();
        if (tid == 0) {
            unsigned gen = g_gen;
            __threadfence();
            if (atomicAdd(&g_cnt, 1u) == NCTA - 1u) {
                g_cnt = 0; __threadfence(); g_gen = gen + 1;
            } else {
                while (g_gen == gen) { __nanosleep(32); }
            }
            __threadfence();
        }
        __syncthreads();
    };

    // ================= phase 0: x -> fp16 =================
    {
        const size_t n4 = (size_t)BB * TT * DD / 4;
        for (size_t i = (size_t)blockIdx.x * 256 + tid; i < n4;
             i += (size_t)NCTA * 256) {
            float4 v = reinterpret_cast<const float4*>(x)[i];
            __half2 h01 = __floats2half2_rn(v.x, v.y);
            __half2 h23 = __floats2half2_rn(v.z, v.w);
            uint2 st;
            st.x = *reinterpret_cast<unsigned*>(&h01);
            st.y = *reinterpret_cast<unsigned*>(&h23);
            reinterpret_cast<uint2*>(g_xh)[i] = st;
        }
    }
    grid_bar();

    // ================= phase 1: xg = x@Wx + b (8 tiles per CTA) =================
    for (int sub = 0; sub < 8; sub++) {
        const int tile = blockIdx.x * 8 + sub;
        const int ns = tile & 127, mg = tile >> 7;
        const int ux = ns * 8;

        __syncthreads();
        // load Wx slice (32 x XG_WS fp16, k-permuted) into Wt region
        for (int i = tid; i < 32 * 512; i += 256) {
            int n = i & 31, slotg = i >> 5;
            int k = (slotg & ~31) + slot_perm(slotg & 31);
            int col = (n >> 3) * UU + ux + (n & 7);
            Wt[n * XG_WS + slotg] = __float2half_rn(Wx[(size_t)k * G4 + col]);
        }
        __syncthreads();

        const unsigned WtB = smem_u32(Wt);
        const unsigned bAddrBase = WtB
            + (unsigned)(no + ((lane >> 4) << 3) + (lane & 7)) * (XG_WS * 2)
            + ((lane >> 3) & 1) * 16;
        float bv[2][2];
#pragma unroll
        for (int j = 0; j < 2; j++) {
            int cl = no + j * 8 + 2 * lc;
            int colg = (cl >> 3) * UU + ux + (cl & 7);
            bv[j][0] = bias[colg]; bv[j][1] = bias[colg + 1];
        }

        for (int mt = 0; mt < 64; mt++) {
            const int r0 = mg * 4096 + mt * 64;
            const __half* pr0 = g_xh + (size_t)(r0 + mo + lr) * DD + 8 * lc;
            const __half* pr1 = pr0 + 8 * DD;
            float acc[2][4];
#pragma unroll
            for (int j = 0; j < 2; j++)
#pragma unroll
                for (int i = 0; i < 4; i++) acc[j][i] = 0.0f;
            uint4 a0c = *reinterpret_cast<const uint4*>(pr0);
            uint4 a1c = *reinterpret_cast<const uint4*>(pr1);
            uint4 a0n = *reinterpret_cast<const uint4*>(pr0 + 32);
            uint4 a1n = *reinterpret_cast<const uint4*>(pr1 + 32);
#pragma unroll
            for (int kc = 0; kc < 16; kc++) {
                uint4 a0f = make_uint4(0, 0, 0, 0), a1f = a0f;
                if (kc < 14) {
                    a0f = *reinterpret_cast<const uint4*>(pr0 + (kc + 2) * 32);
                    a1f = *reinterpret_cast<const uint4*>(pr1 + (kc + 2) * 32);
                }
                const unsigned ba = bAddrBase + kc * 64;
                uint4 B0 = ldsm4(ba);
                uint4 B1 = ldsm4(ba + 32);
                mma16(acc[0], a0c.x, a1c.x, a0c.y, a1c.y, B0.x, B0.y);
                mma16(acc[1], a0c.x, a1c.x, a0c.y, a1c.y, B0.z, B0.w);
                mma16(acc[0], a0c.z, a1c.z, a0c.w, a1c.w, B1.x, B1.y);
                mma16(acc[1], a0c.z, a1c.z, a0c.w, a1c.w, B1.z, B1.w);
                a0c = a0n; a1c = a1n; a0n = a0f; a1n = a1f;
            }
            const int rA = r0 + mo + lr, rB = rA + 8;
            const size_t row0 = (size_t)((rA & (TT - 1)) * BB + (rA >> 9)) * G4;
            const size_t row1 = (size_t)((rB & (TT - 1)) * BB + (rB >> 9)) * G4;
#pragma unroll
            for (int j = 0; j < 2; j++) {
                int cl = no + j * 8 + 2 * lc;
                int colg = (cl >> 3) * UU + ux + (cl & 7);
                *reinterpret_cast<float2*>(&g_xg[row0 + colg]) =
                    make_float2(acc[j][0] + bv[j][0], acc[j][1] + bv[j][1]);
                *reinterpret_cast<float2*>(&g_xg[row1 + colg]) =
                    make_float2(acc[j][2] + bv[j][0], acc[j][3] + bv[j][1]);
            }
        }
    }
    grid_bar();

    // ================= phase 2: recurrence (R10 verbatim) =================
    for (int i = tid; i < 32 * 1024; i += 256) {
        int n = i & 31, k = i >> 5;
        int col = (n >> 3) * UU + u0 + (n & 7);
        Wt[n * WT_STRIDE + k] = __float2half_rn(Wh[(size_t)k * G4 + col]);
    }
    for (int i = tid; i < 512; i += 256)
        Cl[i] = c0[(i >> 3) * UU + u0 + (i & 7)];
    for (int i = blockIdx.x * 256 + tid; i < BB * UU; i += NCTA * 256)
        g_hh[0][i] = __float2half_rn(h0[i]);
    grid_bar();

    const unsigned HsB = smem_u32(Hs);
    const unsigned WtB2 = smem_u32(Wt);

    const unsigned aBase = HsB
        + (unsigned)((mo + (lane & 15)) * HS_STRIDE + (lane >> 4) * 8) * 2u;
    const unsigned bBase = WtB2
        + (unsigned)((no + ((lane >> 4) << 3) + (lane & 7)) * WT_STRIDE
                     + ((lane >> 3) & 1) * 8) * 2u;

    const int cprow = tid >> 2, cpseg = tid & 3;
    const unsigned cpDst = HsB + (unsigned)(cprow * HS_STRIDE + cpseg * 8) * 2u;

    float2 xv[2][2];
#pragma unroll
    for (int j = 0; j < 2; j++) {
        int cl = no + j * 8 + 2 * lc;
        int colg = (cl >> 3) * UU + u0 + (cl & 7);
        xv[j][0] = *reinterpret_cast<const float2*>(&g_xg[(size_t)(mo + lr) * G4 + colg]);
        xv[j][1] = *reinterpret_cast<const float2*>(&g_xg[(size_t)(mo + lr + 8) * G4 + colg]);
    }

    for (int t = 0; t < TT; t++) {
        const __half* __restrict__ hc = g_hh[t & 1];
        __half*       __restrict__ hn = g_hh[(t + 1) & 1];

        const __half* cpSrc = hc + (size_t)cprow * UU + cpseg * 8;
#pragma unroll
        for (int kc = 0; kc < 32; kc++) {
            cp16(cpDst + kc * 64, cpSrc + kc * 32);
            cp_commit();
        }

        float acc[2][2][4];
#pragma unroll
        for (int p = 0; p < 2; p++)
#pragma unroll
            for (int j = 0; j < 2; j++)
#pragma unroll
                for (int i = 0; i < 4; i++) acc[p][j][i] = 0.0f;

        asm volatile("cp.async.wait_group 16;");
        __syncthreads();
#pragma unroll
        for (int kc = 0; kc < 16; kc++) {
            uint4 A0 = ldsm4(aBase + kc * 64);
            uint4 A1 = ldsm4(aBase + kc * 64 + 32);
            uint4 B0 = ldsm4(bBase + kc * 64);
            uint4 B1 = ldsm4(bBase + kc * 64 + 32);
            mma16(acc[0][0], A0.x, A0.y, A0.z, A0.w, B0.x, B0.y);
            mma16(acc[0][1], A0.x, A0.y, A0.z, A0.w, B0.z, B0.w);
            mma16(acc[1][0], A1.x, A1.y, A1.z, A1.w, B1.x, B1.y);
            mma16(acc[1][1], A1.x, A1.y, A1.z, A1.w, B1.z, B1.w);
        }
        asm volatile("cp.async.wait_group 0;");
        __syncthreads();
#pragma unroll
        for (int kc = 16; kc < 32; kc++) {
            uint4 A0 = ldsm4(aBase + kc * 64);
            uint4 A1 = ldsm4(aBase + kc * 64 + 32);
            uint4 B0 = ldsm4(bBase + kc * 64);
            uint4 B1 = ldsm4(bBase + kc * 64 + 32);
            mma16(acc[0][0], A0.x, A0.y, A0.z, A0.w, B0.x, B0.y);
            mma16(acc[0][1], A0.x, A0.y, A0.z, A0.w, B0.z, B0.w);
            mma16(acc[1][0], A1.x, A1.y, A1.z, A1.w, B1.x, B1.y);
            mma16(acc[1][1], A1.x, A1.y, A1.z, A1.w, B1.z, B1.w);
        }

        const int rA = mo + lr;
#pragma unroll
        for (int j = 0; j < 2; j++) {
            int cl = no + j * 8 + 2 * lc;
            Gs[rA * 33 + cl]           = acc[0][j][0] + acc[1][j][0] + xv[j][0].x;
            Gs[rA * 33 + cl + 1]       = acc[0][j][1] + acc[1][j][1] + xv[j][0].y;
            Gs[(rA + 8) * 33 + cl]     = acc[0][j][2] + acc[1][j][2] + xv[j][1].x;
            Gs[(rA + 8) * 33 + cl + 1] = acc[0][j][3] + acc[1][j][3] + xv[j][1].y;
        }
        __syncthreads();

#pragma unroll
        for (int q = 0; q < 2; q++) {
            int e  = tid + q * 256;
            int m  = e >> 3, du = e & 7;
            float gi = fsig  (Gs[m * 33 + 0 * 8 + du]);
            float gf = fsig  (Gs[m * 33 + 1 * 8 + du]);
            float gg = ftanh_(Gs[m * 33 + 2 * 8 + du]);
            float go = fsig  (Gs[m * 33 + 3 * 8 + du]);
            float cv = gf * Cl[e] + gi * gg;
            Cl[e] = cv;
            float hv = go * ftanh_(cv);
            hn[m * UU + u0 + du] = __float2half_rn(hv);
            if (t == TT - 1) out[m * UU + u0 + du] = hv;
        }
        __syncthreads();

        unsigned gen;
        if (tid == 0) {
            gen = g_gen;
            __threadfence();
            if (atomicAdd(&g_cnt, 1u) == NCTA - 1u) {
                g_cnt = 0; __threadfence(); g_gen = gen + 1;
            }
        }
        if (t + 1 < TT) {
            const size_t base = (size_t)(t + 1) * BB * G4;
#pragma unroll
            for (int j = 0; j < 2; j++) {
                int cl = no + j * 8 + 2 * lc;
                int colg = (cl >> 3) * UU + u0 + (cl & 7);
                xv[j][0] = *reinterpret_cast<const float2*>(
                    &g_xg[base + (size_t)(mo + lr) * G4 + colg]);
                xv[j][1] = *reinterpret_cast<const float2*>(
                    &g_xg[base + (size_t)(mo + lr + 8) * G4 + colg]);
            }
        }
        if (tid == 0) {
            while (g_gen == gen) { __nanosleep(32); }
            __threadfence();
        }
        __syncthreads();
    }
}

// ============================================================================
extern "C" void kernel_launch(void* const* d_in, const int* in_sizes, int n_in,
                              void* d_out, int out_size)
{
    const float* x  = (const float*)d_in[0];
    const float* h0 = (const float*)d_in[1];
    const float* c0 = (const float*)d_in[2];
    const float* Wx = (const float*)d_in[3];
    const float* Wh = (const float*)d_in[4];
    const float* b  = (const float*)d_in[5];
    float* out = (float*)d_out;

    cudaFuncSetAttribute(lstm_persist, cudaFuncAttributeMaxDynamicSharedMemorySize,
                         SMEM_BYTES);
    lstm_persist<<<NCTA, 256, SMEM_BYTES>>>(x, Wx, b, Wh, h0, c0, out);

    (void)in_sizes; (void)n_in; (void)out_size;
}

// round 16
// speedup vs baseline: 1.2117x; 1.2117x over previous
#include <cuda_runtime.h>
#include <cuda_fp16.h>
#include <math.h>
#include <stdint.h>

#define BB   64
#define TT   512
#define DD   512
#define UU   1024
#define G4   4096
#define NCTA 128

__device__ float  g_xg[(size_t)BB * TT * G4];   // [t][b][4096]
__device__ __align__(16) __half g_xh[(size_t)BB * TT * DD];
__device__ __align__(16) __half g_hh[2][BB * UU];
__device__ volatile unsigned g_gen; __device__ unsigned g_pad1[31];
__device__ unsigned g_cnt;          __device__ unsigned g_pad2[31];

// ---------------- helpers ---------------------------------------------------
__device__ __forceinline__ void mma16(float c[4], unsigned a0, unsigned a1,
                                      unsigned a2, unsigned a3,
                                      unsigned b0, unsigned b1) {
    asm volatile(
        "mma.sync.aligned.m16n8k16.row.col.f32.f16.f16.f32 "
        "{%0,%1,%2,%3}, {%4,%5,%6,%7}, {%8,%9}, {%0,%1,%2,%3};"
        : "+f"(c[0]), "+f"(c[1]), "+f"(c[2]), "+f"(c[3])
        : "r"(a0), "r"(a1), "r"(a2), "r"(a3), "r"(b0), "r"(b1));
}
__device__ __forceinline__ uint4 ldsm4(unsigned addr) {
    uint4 r;
    asm volatile("ldmatrix.sync.aligned.m8n8.x4.shared.b16 {%0,%1,%2,%3}, [%4];"
                 : "=r"(r.x), "=r"(r.y), "=r"(r.z), "=r"(r.w) : "r"(addr));
    return r;
}
__device__ __forceinline__ void cp16(unsigned dst, const void* src) {
    asm volatile("cp.async.cg.shared.global [%0], [%1], 16;" :: "r"(dst), "l"(src));
}
__device__ __forceinline__ void cp_commit() {
    asm volatile("cp.async.commit_group;");
}
__device__ __forceinline__ unsigned smem_u32(const void* p) {
    unsigned a;
    asm("{ .reg .u64 t; cvta.to.shared.u64 t, %1; cvt.u32.u64 %0, t; }" : "=r"(a) : "l"(p));
    return a;
}
__device__ __forceinline__ int slot_perm(int slot5) {
    int s = slot5 >> 4, p = slot5 & 15;
    int lcp = (p < 8) ? (p >> 1) : ((p - 8) >> 1);
    int add = (p < 8) ? 0 : 2;
    return 8 * lcp + 4 * s + add + (p & 1);
}
// fast activations (R9/R10-validated)
__device__ __forceinline__ float fsig(float x) {
    float e, r;
    asm("ex2.approx.f32 %0, %1;" : "=f"(e) : "f"(-1.4426950408889634f * x));
    asm("rcp.approx.f32 %0, %1;" : "=f"(r) : "f"(1.0f + e));
    return r;
}
__device__ __forceinline__ float ftanh_(float x) {
    float e, r;
    asm("ex2.approx.f32 %0, %1;" : "=f"(e) : "f"(2.8853900817779268f * x));
    asm("rcp.approx.f32 %0, %1;" : "=f"(r) : "f"(1.0f + e));
    return 1.0f - 2.0f * r;
}

// ========================== conv_x ==========================
__global__ __launch_bounds__(256) void conv_x(const float* __restrict__ x) {
    const size_t n4 = (size_t)BB * TT * DD / 4;
    for (size_t i = (size_t)blockIdx.x * 256 + threadIdx.x; i < n4;
         i += (size_t)gridDim.x * 256) {
        float4 v = reinterpret_cast<const float4*>(x)[i];
        __half2 h01 = __floats2half2_rn(v.x, v.y);
        __half2 h23 = __floats2half2_rn(v.z, v.w);
        uint2 st;
        st.x = *reinterpret_cast<unsigned*>(&h01);
        st.y = *reinterpret_cast<unsigned*>(&h23);
        reinterpret_cast<uint2*>(g_xh)[i] = st;
    }
}

// ================= xg_kernel (R3-validated, 1024 CTAs) =================
#define XG_WT_STRIDE 520
__global__ __launch_bounds__(256) void xg_kernel(
    const float* __restrict__ Wx, const float* __restrict__ bias)
{
    __shared__ __half Wt[32 * XG_WT_STRIDE];
    const int tid = threadIdx.x, warp = tid >> 5, lane = tid & 31;
    const int lr = lane >> 2, lc = lane & 3;
    const int mo = (warp & 3) * 16, no = (warp >> 2) * 16;
    const int ns = blockIdx.x & 127, mg = blockIdx.x >> 7, u0 = ns * 8;

    for (int i = tid; i < 32 * 512; i += 256) {
        int n = i & 31, slotg = i >> 5;
        int k = (slotg & ~31) + slot_perm(slotg & 31);
        int col = (n >> 3) * UU + u0 + (n & 7);
        Wt[n * XG_WT_STRIDE + slotg] = __float2half_rn(Wx[(size_t)k * G4 + col]);
    }
    __syncthreads();
    const unsigned WtB = smem_u32(Wt);
    const unsigned bAddrBase = WtB
        + (unsigned)(no + ((lane >> 4) << 3) + (lane & 7)) * (XG_WT_STRIDE * 2)
        + ((lane >> 3) & 1) * 16;
    float bv[2][2];
#pragma unroll
    for (int j = 0; j < 2; j++) {
        int cl = no + j * 8 + 2 * lc;
        int colg = (cl >> 3) * UU + u0 + (cl & 7);
        bv[j][0] = bias[colg]; bv[j][1] = bias[colg + 1];
    }
    for (int mt = 0; mt < 64; mt++) {
        const int r0 = mg * 4096 + mt * 64;
        const __half* pr0 = g_xh + (size_t)(r0 + mo + lr) * DD + 8 * lc;
        const __half* pr1 = pr0 + 8 * DD;
        float acc[2][4];
#pragma unroll
        for (int j = 0; j < 2; j++)
#pragma unroll
            for (int i = 0; i < 4; i++) acc[j][i] = 0.0f;
        uint4 a0c = *reinterpret_cast<const uint4*>(pr0);
        uint4 a1c = *reinterpret_cast<const uint4*>(pr1);
        uint4 a0n = *reinterpret_cast<const uint4*>(pr0 + 32);
        uint4 a1n = *reinterpret_cast<const uint4*>(pr1 + 32);
#pragma unroll
        for (int kc = 0; kc < 16; kc++) {
            uint4 a0f = make_uint4(0, 0, 0, 0), a1f = a0f;
            if (kc < 14) {
                a0f = *reinterpret_cast<const uint4*>(pr0 + (kc + 2) * 32);
                a1f = *reinterpret_cast<const uint4*>(pr1 + (kc + 2) * 32);
            }
            const unsigned ba = bAddrBase + kc * 64;
            uint4 B0 = ldsm4(ba);
            uint4 B1 = ldsm4(ba + 32);
            mma16(acc[0], a0c.x, a1c.x, a0c.y, a1c.y, B0.x, B0.y);
            mma16(acc[1], a0c.x, a1c.x, a0c.y, a1c.y, B0.z, B0.w);
            mma16(acc[0], a0c.z, a1c.z, a0c.w, a1c.w, B1.x, B1.y);
            mma16(acc[1], a0c.z, a1c.z, a0c.w, a1c.w, B1.z, B1.w);
            a0c = a0n; a1c = a1n; a0n = a0f; a1n = a1f;
        }
        const int rA = r0 + mo + lr, rB = rA + 8;
        const size_t row0 = (size_t)((rA & (TT - 1)) * BB + (rA >> 9)) * G4;
        const size_t row1 = (size_t)((rB & (TT - 1)) * BB + (rB >> 9)) * G4;
#pragma unroll
        for (int j = 0; j < 2; j++) {
            int cl = no + j * 8 + 2 * lc;
            int colg = (cl >> 3) * UU + u0 + (cl & 7);
            *reinterpret_cast<float2*>(&g_xg[row0 + colg]) =
                make_float2(acc[j][0] + bv[j][0], acc[j][1] + bv[j][1]);
            *reinterpret_cast<float2*>(&g_xg[row1 + colg]) =
                make_float2(acc[j][2] + bv[j][0], acc[j][3] + bv[j][1]);
        }
    }
}

// ===== persistent LSTM step kernel (R10 + hot-spin polls + quarter waits) =====
#define HS_STRIDE 1032
#define WT_STRIDE 1032
#define WT_BYTES  (32 * WT_STRIDE * 2)
#define HS_BYTES  (64 * HS_STRIDE * 2)
#define SMEM_BYTES (WT_BYTES + HS_BYTES + 64 * 33 * 4 + 512 * 4)

__global__ __launch_bounds__(256) void lstm_persist(
    const float* __restrict__ Wh, const float* __restrict__ h0,
    const float* __restrict__ c0, float* __restrict__ out)
{
    extern __shared__ char smraw[];
    __half* Wt = (__half*)smraw;
    __half* Hs = (__half*)(smraw + WT_BYTES);
    float*  Gs = (float*)(smraw + WT_BYTES + HS_BYTES);
    float*  Cl = Gs + 64 * 33;

    const int tid  = threadIdx.x;
    const int warp = tid >> 5, lane = tid & 31;
    const int lr = lane >> 2, lc = lane & 3;
    const int mo = (warp & 3) * 16;
    const int no = (warp >> 2) * 16;
    const int u0 = blockIdx.x * 8;

    for (int i = tid; i < 32 * 1024; i += 256) {
        int n = i & 31, k = i >> 5;
        int col = (n >> 3) * UU + u0 + (n & 7);
        Wt[n * WT_STRIDE + k] = __float2half_rn(Wh[(size_t)k * G4 + col]);
    }
    for (int i = tid; i < 512; i += 256)
        Cl[i] = c0[(i >> 3) * UU + u0 + (i & 7)];
    for (int i = blockIdx.x * 256 + tid; i < BB * UU; i += NCTA * 256)
        g_hh[0][i] = __float2half_rn(h0[i]);
    __syncthreads();

    if (tid == 0) {                          // initial grid barrier (hot spin)
        unsigned gen = g_gen;
        __threadfence();
        if (atomicAdd(&g_cnt, 1u) == NCTA - 1u) {
            g_cnt = 0; __threadfence(); g_gen = gen + 1;
        } else {
            while (g_gen == gen) { }
        }
        __threadfence();
    }
    __syncthreads();

    const unsigned HsB = smem_u32(Hs);
    const unsigned WtB = smem_u32(Wt);

    const unsigned aBase = HsB
        + (unsigned)((mo + (lane & 15)) * HS_STRIDE + (lane >> 4) * 8) * 2u;
    const unsigned bBase = WtB
        + (unsigned)((no + ((lane >> 4) << 3) + (lane & 7)) * WT_STRIDE
                     + ((lane >> 3) & 1) * 8) * 2u;

    const int cprow = tid >> 2, cpseg = tid & 3;
    const unsigned cpDst = HsB + (unsigned)(cprow * HS_STRIDE + cpseg * 8) * 2u;

    float2 xv[2][2];
#pragma unroll
    for (int j = 0; j < 2; j++) {
        int cl = no + j * 8 + 2 * lc;
        int colg = (cl >> 3) * UU + u0 + (cl & 7);
        xv[j][0] = *reinterpret_cast<const float2*>(&g_xg[(size_t)(mo + lr) * G4 + colg]);
        xv[j][1] = *reinterpret_cast<const float2*>(&g_xg[(size_t)(mo + lr + 8) * G4 + colg]);
    }

    for (int t = 0; t < TT; t++) {
        const __half* __restrict__ hc = g_hh[t & 1];
        __half*       __restrict__ hn = g_hh[(t + 1) & 1];

        const __half* cpSrc = hc + (size_t)cprow * UU + cpseg * 8;
#pragma unroll
        for (int kc = 0; kc < 32; kc++) {
            cp16(cpDst + kc * 64, cpSrc + kc * 32);
            cp_commit();
        }

        float acc[2][2][4];
#pragma unroll
        for (int p = 0; p < 2; p++)
#pragma unroll
            for (int j = 0; j < 2; j++)
#pragma unroll
                for (int i = 0; i < 4; i++) acc[p][j][i] = 0.0f;

        // quarter-granularity waits: compute starts after first 8 chunks land
#pragma unroll
        for (int qb = 0; qb < 4; qb++) {
            switch (qb) {
                case 0: asm volatile("cp.async.wait_group 24;"); break;
                case 1: asm volatile("cp.async.wait_group 16;"); break;
                case 2: asm volatile("cp.async.wait_group 8;");  break;
                default: asm volatile("cp.async.wait_group 0;"); break;
            }
            __syncthreads();
#pragma unroll
            for (int q = 0; q < 8; q++) {
                const int kc = qb * 8 + q;
                uint4 A0 = ldsm4(aBase + kc * 64);
                uint4 A1 = ldsm4(aBase + kc * 64 + 32);
                uint4 B0 = ldsm4(bBase + kc * 64);
                uint4 B1 = ldsm4(bBase + kc * 64 + 32);
                mma16(acc[0][0], A0.x, A0.y, A0.z, A0.w, B0.x, B0.y);
                mma16(acc[0][1], A0.x, A0.y, A0.z, A0.w, B0.z, B0.w);
                mma16(acc[1][0], A1.x, A1.y, A1.z, A1.w, B1.x, B1.y);
                mma16(acc[1][1], A1.x, A1.y, A1.z, A1.w, B1.z, B1.w);
            }
        }

        const int rA = mo + lr;
#pragma unroll
        for (int j = 0; j < 2; j++) {
            int cl = no + j * 8 + 2 * lc;
            Gs[rA * 33 + cl]           = acc[0][j][0] + acc[1][j][0] + xv[j][0].x;
            Gs[rA * 33 + cl + 1]       = acc[0][j][1] + acc[1][j][1] + xv[j][0].y;
            Gs[(rA + 8) * 33 + cl]     = acc[0][j][2] + acc[1][j][2] + xv[j][1].x;
            Gs[(rA + 8) * 33 + cl + 1] = acc[0][j][3] + acc[1][j][3] + xv[j][1].y;
        }
        __syncthreads();

#pragma unroll
        for (int q = 0; q < 2; q++) {
            int e  = tid + q * 256;
            int m  = e >> 3, du = e & 7;
            float gi = fsig  (Gs[m * 33 + 0 * 8 + du]);
            float gf = fsig  (Gs[m * 33 + 1 * 8 + du]);
            float gg = ftanh_(Gs[m * 33 + 2 * 8 + du]);
            float go = fsig  (Gs[m * 33 + 3 * 8 + du]);
            float cv = gf * Cl[e] + gi * gg;
            Cl[e] = cv;
            float hv = go * ftanh_(cv);
            hn[m * UU + u0 + du] = __float2half_rn(hv);
            if (t == TT - 1) out[m * UU + u0 + du] = hv;
        }
        __syncthreads();

        unsigned gen;
        if (tid == 0) {
            gen = g_gen;
            __threadfence();
            if (atomicAdd(&g_cnt, 1u) == NCTA - 1u) {
                g_cnt = 0; __threadfence(); g_gen = gen + 1;
            }
        }
        if (t + 1 < TT) {
            const size_t base = (size_t)(t + 1) * BB * G4;
#pragma unroll
            for (int j = 0; j < 2; j++) {
                int cl = no + j * 8 + 2 * lc;
                int colg = (cl >> 3) * UU + u0 + (cl & 7);
                xv[j][0] = *reinterpret_cast<const float2*>(
                    &g_xg[base + (size_t)(mo + lr) * G4 + colg]);
                xv[j][1] = *reinterpret_cast<const float2*>(
                    &g_xg[base + (size_t)(mo + lr + 8) * G4 + colg]);
            }
        }
        if (tid == 0) {
            while (g_gen == gen) { }         // hot spin, no nanosleep
            __threadfence();
        }
        __syncthreads();
    }
}

// ============================================================================
extern "C" void kernel_launch(void* const* d_in, const int* in_sizes, int n_in,
                              void* d_out, int out_size)
{
    const float* x  = (const float*)d_in[0];
    const float* h0 = (const float*)d_in[1];
    const float* c0 = (const float*)d_in[2];
    const float* Wx = (const float*)d_in[3];
    const float* Wh = (const float*)d_in[4];
    const float* b  = (const float*)d_in[5];
    float* out = (float*)d_out;

    conv_x<<<4096, 256>>>(x);
    xg_kernel<<<1024, 256>>>(Wx, b);

    cudaFuncSetAttribute(lstm_persist, cudaFuncAttributeMaxDynamicSharedMemorySize,
                         SMEM_BYTES);
    lstm_persist<<<NCTA, 256, SMEM_BYTES>>>(Wh, h0, c0, out);

    (void)in_sizes; (void)n_in; (void)out_size;
}